// round 1
// baseline (speedup 1.0000x reference)
#include <cuda_runtime.h>
#include <cuda_bf16.h>

#define NN 50000
#define EE 800000
#define GG 1000
#define HH 128
#define LL 3
#define CC 6
#define EPS 1e-5f

// ---------------- scratch (device globals; no allocation allowed) ----------------
__device__ float g_deg[NN];
__device__ float g_dis[NN];
__device__ float g_selfnorm[NN];
__device__ float g_edgenorm[EE];
__device__ float g_h[NN * HH];     // h = x @ W
__device__ float g_agg[NN * HH];   // aggregated + self + bias
__device__ float g_x[NN * HH];     // layer activations
__device__ float g_sum[HH];
__device__ float g_sumsq[HH];
__device__ float g_pool[GG * HH];
__device__ float g_cnt[GG];

// ---------------- degree / norm precompute ----------------
__global__ void k_deg_init() {
    int n = blockIdx.x * blockDim.x + threadIdx.x;
    if (n < NN) g_deg[n] = 1.0f;   // +1 for self loop
}

__global__ void k_deg_count(const int* __restrict__ dst) {
    int e = blockIdx.x * blockDim.x + threadIdx.x;
    if (e < EE) atomicAdd(&g_deg[dst[e]], 1.0f);
}

__global__ void k_norm() {
    int n = blockIdx.x * blockDim.x + threadIdx.x;
    if (n < NN) {
        float d = rsqrtf(g_deg[n]);
        g_dis[n] = d;
        g_selfnorm[n] = d * d;
    }
}

__global__ void k_edgenorm(const int* __restrict__ src, const int* __restrict__ dst) {
    int e = blockIdx.x * blockDim.x + threadIdx.x;
    if (e < EE) g_edgenorm[e] = g_dis[src[e]] * g_dis[dst[e]];
}

// ---------------- GEMM: g_h = A[N,128] @ B[128,128] ----------------
// A == nullptr means "read from g_x"
__global__ void k_gemm(const float* __restrict__ Ain, const float* __restrict__ B) {
    const float* __restrict__ A = Ain ? Ain : g_x;
    __shared__ float As[64 * 32];
    __shared__ float Bs[32 * 64];
    int row0 = blockIdx.x * 64;
    int col0 = blockIdx.y * 64;
    int t = threadIdx.x;          // 0..255
    int tx = t & 15, ty = t >> 4; // 16 x 16
    float acc[4][4] = {};

    for (int k0 = 0; k0 < 128; k0 += 32) {
        // load A tile 64x32 (512 float4, 2 per thread)
#pragma unroll
        for (int i = 0; i < 2; i++) {
            int fi = t + i * 256;
            int r = fi >> 3;      // 8 float4 per row
            int kq = fi & 7;
            float4 v = make_float4(0.f, 0.f, 0.f, 0.f);
            int grow = row0 + r;
            if (grow < NN) v = *(const float4*)&A[grow * 128 + k0 + kq * 4];
            *(float4*)&As[r * 32 + kq * 4] = v;
        }
        // load B tile 32x64
#pragma unroll
        for (int i = 0; i < 2; i++) {
            int fi = t + i * 256;
            int kr = fi >> 4;     // 16 float4 per row
            int cq = fi & 15;
            float4 v = *(const float4*)&B[(k0 + kr) * 128 + col0 + cq * 4];
            *(float4*)&Bs[kr * 64 + cq * 4] = v;
        }
        __syncthreads();
#pragma unroll
        for (int kk = 0; kk < 32; kk++) {
            float a[4], b[4];
            float4 bv = *(float4*)&Bs[kk * 64 + tx * 4];
            b[0] = bv.x; b[1] = bv.y; b[2] = bv.z; b[3] = bv.w;
#pragma unroll
            for (int i = 0; i < 4; i++) a[i] = As[(ty * 4 + i) * 32 + kk];
#pragma unroll
            for (int i = 0; i < 4; i++)
#pragma unroll
                for (int j = 0; j < 4; j++) acc[i][j] += a[i] * b[j];
        }
        __syncthreads();
    }
#pragma unroll
    for (int i = 0; i < 4; i++) {
        int grow = row0 + ty * 4 + i;
        if (grow < NN) {
            float4 v = make_float4(acc[i][0], acc[i][1], acc[i][2], acc[i][3]);
            *(float4*)&g_h[grow * 128 + col0 + tx * 4] = v;
        }
    }
}

// ---------------- agg init: agg = h * selfnorm + bias ----------------
__global__ void k_agg_init(const float* __restrict__ bias) {
    int t = blockIdx.x * blockDim.x + threadIdx.x;   // N*32 threads
    int n = t >> 5, q = t & 31;
    if (n >= NN) return;
    float sn = g_selfnorm[n];
    float4 v = ((const float4*)(g_h))[n * 32 + q];
    float4 b = ((const float4*)(bias))[q];
    float4 o;
    o.x = v.x * sn + b.x;
    o.y = v.y * sn + b.y;
    o.z = v.z * sn + b.z;
    o.w = v.w * sn + b.w;
    ((float4*)(g_agg))[n * 32 + q] = o;
}

// ---------------- scatter: agg[dst] += h[src] * edgenorm, via red.v4 ----------------
__global__ void k_scatter(const int* __restrict__ src, const int* __restrict__ dst) {
    int t = blockIdx.x * blockDim.x + threadIdx.x;   // E*32 threads (warp per edge)
    int e = t >> 5, q = t & 31;
    if (e >= EE) return;
    int s = src[e];
    int d = dst[e];
    float w = g_edgenorm[e];
    float4 v = ((const float4*)(g_h))[s * 32 + q];
    float* out = g_agg + (size_t)d * HH + q * 4;
    asm volatile("red.global.add.v4.f32 [%0], {%1,%2,%3,%4};"
                 :: "l"(out), "f"(v.x * w), "f"(v.y * w), "f"(v.z * w), "f"(v.w * w)
                 : "memory");
}

// ---------------- BN stats ----------------
__global__ void k_zero_stats() {
    int t = threadIdx.x;
    g_sum[t] = 0.0f;
    g_sumsq[t] = 0.0f;
}

__global__ void k_bnstats() {
    int c = threadIdx.x;            // 128 threads, one channel each
    float s = 0.0f, ss = 0.0f;
    for (int n = blockIdx.x; n < NN; n += gridDim.x) {
        float v = g_agg[n * HH + c];
        s += v;
        ss += v * v;
    }
    atomicAdd(&g_sum[c], s);
    atomicAdd(&g_sumsq[c], ss);
}

// ---------------- BN apply + relu -> g_x ----------------
__global__ void k_bnapply(const float* __restrict__ gamma, const float* __restrict__ beta) {
    int t = blockIdx.x * blockDim.x + threadIdx.x;   // N*32 threads
    int n = t >> 5, q = t & 31;
    if (n >= NN) return;
    float4 v  = ((const float4*)(g_agg))[n * 32 + q];
    float4 sm = ((const float4*)(g_sum))[q];
    float4 sq = ((const float4*)(g_sumsq))[q];
    float4 ga = ((const float4*)(gamma))[q];
    float4 be = ((const float4*)(beta))[q];
    const float invN = 1.0f / (float)NN;
    float4 o;
    {
        float mu = sm.x * invN; float var = sq.x * invN - mu * mu;
        o.x = fmaxf((v.x - mu) * rsqrtf(var + EPS) * ga.x + be.x, 0.0f);
    }
    {
        float mu = sm.y * invN; float var = sq.y * invN - mu * mu;
        o.y = fmaxf((v.y - mu) * rsqrtf(var + EPS) * ga.y + be.y, 0.0f);
    }
    {
        float mu = sm.z * invN; float var = sq.z * invN - mu * mu;
        o.z = fmaxf((v.z - mu) * rsqrtf(var + EPS) * ga.z + be.z, 0.0f);
    }
    {
        float mu = sm.w * invN; float var = sq.w * invN - mu * mu;
        o.w = fmaxf((v.w - mu) * rsqrtf(var + EPS) * ga.w + be.w, 0.0f);
    }
    ((float4*)(g_x))[n * 32 + q] = o;
}

// ---------------- pooling ----------------
__global__ void k_pool_zero() {
    int t = blockIdx.x * blockDim.x + threadIdx.x;
    if (t < GG * HH) g_pool[t] = 0.0f;
    if (t < GG) g_cnt[t] = 0.0f;
}

__global__ void k_pool(const int* __restrict__ batch) {
    int t = blockIdx.x * blockDim.x + threadIdx.x;   // N*32 threads
    int n = t >> 5, q = t & 31;
    if (n >= NN) return;
    int g = batch[n];
    float4 v = ((const float4*)(g_x))[n * 32 + q];
    float* out = g_pool + (size_t)g * HH + q * 4;
    asm volatile("red.global.add.v4.f32 [%0], {%1,%2,%3,%4};"
                 :: "l"(out), "f"(v.x), "f"(v.y), "f"(v.z), "f"(v.w)
                 : "memory");
    if (q == 0) atomicAdd(&g_cnt[g], 1.0f);
}

// ---------------- MLP head: one block per graph ----------------
__global__ void k_mlp(const float* __restrict__ w1, const float* __restrict__ b1,
                      const float* __restrict__ w2, const float* __restrict__ b2,
                      float* __restrict__ out) {
    int g = blockIdx.x;
    int t = threadIdx.x;       // 128
    __shared__ float p[128];
    __shared__ float red[4][8];
    float inv = 1.0f / fmaxf(g_cnt[g], 1.0f);
    p[t] = g_pool[g * HH + t] * inv;
    __syncthreads();
    float acc = b1[t];
#pragma unroll 8
    for (int k = 0; k < 128; k++) acc += p[k] * w1[k * 128 + t];
    float h = fmaxf(acc, 0.0f);
    float pr[CC];
#pragma unroll
    for (int c = 0; c < CC; c++) pr[c] = h * w2[t * CC + c];
#pragma unroll
    for (int off = 16; off > 0; off >>= 1)
#pragma unroll
        for (int c = 0; c < CC; c++) pr[c] += __shfl_down_sync(0xffffffffu, pr[c], off);
    int w = t >> 5, lane = t & 31;
    if (lane == 0)
#pragma unroll
        for (int c = 0; c < CC; c++) red[w][c] = pr[c];
    __syncthreads();
    if (t < CC) {
        out[g * CC + t] = red[0][t] + red[1][t] + red[2][t] + red[3][t] + b2[t];
    }
}

// ---------------- launch ----------------
extern "C" void kernel_launch(void* const* d_in, const int* in_sizes, int n_in,
                              void* d_out, int out_size) {
    const float* x      = (const float*)d_in[0];
    const int*   ei     = (const int*)d_in[1];
    const int*   batch  = (const int*)d_in[2];
    const float* conv_w = (const float*)d_in[3];
    const float* conv_b = (const float*)d_in[4];
    const float* bn_g   = (const float*)d_in[5];
    const float* bn_b   = (const float*)d_in[6];
    const float* w1     = (const float*)d_in[7];
    const float* b1     = (const float*)d_in[8];
    const float* w2     = (const float*)d_in[9];
    const float* b2     = (const float*)d_in[10];
    float* out = (float*)d_out;

    const int* src = ei;
    const int* dst = ei + EE;

    k_deg_init<<<(NN + 255) / 256, 256>>>();
    k_deg_count<<<(EE + 255) / 256, 256>>>(dst);
    k_norm<<<(NN + 255) / 256, 256>>>();
    k_edgenorm<<<(EE + 255) / 256, 256>>>(src, dst);

    dim3 ggrid((NN + 63) / 64, 2);
    const long long nwarp_threads = (long long)NN * 32;
    const int nwarp_blocks = (int)((nwarp_threads + 255) / 256);
    const long long ewarp_threads = (long long)EE * 32;
    const int ewarp_blocks = (int)((ewarp_threads + 255) / 256);

    for (int l = 0; l < LL; l++) {
        const float* A = (l == 0) ? x : nullptr;   // nullptr -> g_x
        k_gemm<<<ggrid, 256>>>(A, conv_w + (size_t)l * HH * HH);
        k_agg_init<<<nwarp_blocks, 256>>>(conv_b + (size_t)l * HH);
        k_scatter<<<ewarp_blocks, 256>>>(src, dst);
        k_zero_stats<<<1, 128>>>();
        k_bnstats<<<1024, 128>>>();
        k_bnapply<<<nwarp_blocks, 256>>>(bn_g + (size_t)l * HH, bn_b + (size_t)l * HH);
    }

    k_pool_zero<<<(GG * HH + 255) / 256, 256>>>();
    k_pool<<<nwarp_blocks, 256>>>(batch);
    k_mlp<<<GG, 128>>>(w1, b1, w2, b2, out);
}

// round 2
// speedup vs baseline: 1.0979x; 1.0979x over previous
#include <cuda_runtime.h>
#include <cuda_bf16.h>

#define NN 50000
#define EE 800000
#define GG 1000
#define HH 128
#define LL 3
#define CC 6
#define EPS 1e-5f

// ---------------- scratch (device globals; no allocation) ----------------
__device__ int   g_degi[NN];
__device__ int   g_rowptr[NN + 1];
__device__ int   g_cursor[NN];
__device__ int   g_csrsrc[EE];
__device__ float g_dis[NN];
__device__ float g_hs[NN * HH];    // h * dis[row]  (GEMM output, pre-scaled)
__device__ float g_agg[NN * HH];   // aggregated + self + bias
__device__ float g_sum[HH];
__device__ float g_sumsq[HH];
__device__ float g_bnscale[HH];
__device__ float g_bnshift[HH];
__device__ float g_pool[GG * HH];
__device__ float g_cnt[GG];

// ---------------- degree / CSR build ----------------
__global__ void k_zero_degi() {
    int n = blockIdx.x * blockDim.x + threadIdx.x;
    if (n < NN) g_degi[n] = 0;
}

__global__ void k_deg_count(const int* __restrict__ dst) {
    int e = blockIdx.x * blockDim.x + threadIdx.x;
    if (e < EE) atomicAdd(&g_degi[dst[e]], 1);
}

__global__ void k_norm() {
    int n = blockIdx.x * blockDim.x + threadIdx.x;
    if (n < NN) g_dis[n] = rsqrtf((float)g_degi[n] + 1.0f);
}

// single-block exclusive scan of g_degi -> g_rowptr / g_cursor
__global__ void k_scan() {
    __shared__ int part[1024];
    int t = threadIdx.x;
    const int CHK = (NN + 1023) / 1024;   // 49
    int base = t * CHK;
    int s = 0;
    for (int i = 0; i < CHK; i++) {
        int n = base + i;
        if (n < NN) s += g_degi[n];
    }
    part[t] = s;
    __syncthreads();
    int val = s;
    for (int off = 1; off < 1024; off <<= 1) {
        int v = (t >= off) ? part[t - off] : 0;
        __syncthreads();
        part[t] += v;
        __syncthreads();
    }
    int run = part[t] - val;   // exclusive prefix
    for (int i = 0; i < CHK; i++) {
        int n = base + i;
        if (n < NN) {
            g_rowptr[n] = run;
            g_cursor[n] = run;
            run += g_degi[n];
        }
    }
    if (t == 1023) g_rowptr[NN] = EE;
}

__global__ void k_fill(const int* __restrict__ src, const int* __restrict__ dst) {
    int e = blockIdx.x * blockDim.x + threadIdx.x;
    if (e < EE) {
        int d = dst[e];
        int pos = atomicAdd(&g_cursor[d], 1);
        g_csrsrc[pos] = src[e];
    }
}

// ---------------- GEMM: g_hs = BN?(A)[N,128] @ B[128,128] * dis[row] ----------------
// A == nullptr -> read g_agg (prev layer) with BN scale/shift + relu prologue
__global__ void __launch_bounds__(256) k_gemm(const float* __restrict__ Ain,
                                              const float* __restrict__ B,
                                              int apply_bn) {
    const float* __restrict__ A = Ain ? Ain : g_agg;
    __shared__ float As[32][64];    // transposed: As[k][row]
    __shared__ float Bs[32][128];
    int row0 = blockIdx.x * 64;
    int t = threadIdx.x;            // 0..255
    int tx = t & 15, ty = t >> 4;   // tx -> 8 cols, ty -> 4 rows
    float acc[4][8] = {};

    for (int k0 = 0; k0 < 128; k0 += 32) {
        // A tile: 64 rows x 32 k  (512 float4, 2 per thread), BN prologue, store transposed
#pragma unroll
        for (int i = 0; i < 2; i++) {
            int fi = t + i * 256;
            int r = fi >> 3;             // 8 float4 per row
            int kq = fi & 7;             // k quad
            int grow = row0 + r;
            float4 v = make_float4(0.f, 0.f, 0.f, 0.f);
            if (grow < NN) v = *(const float4*)&A[grow * 128 + k0 + kq * 4];
            if (apply_bn) {
                float4 sc = ((const float4*)g_bnscale)[(k0 >> 2) + kq];
                float4 sh = ((const float4*)g_bnshift)[(k0 >> 2) + kq];
                v.x = fmaxf(v.x * sc.x + sh.x, 0.f);
                v.y = fmaxf(v.y * sc.y + sh.y, 0.f);
                v.z = fmaxf(v.z * sc.z + sh.z, 0.f);
                v.w = fmaxf(v.w * sc.w + sh.w, 0.f);
            }
            As[kq * 4 + 0][r] = v.x;
            As[kq * 4 + 1][r] = v.y;
            As[kq * 4 + 2][r] = v.z;
            As[kq * 4 + 3][r] = v.w;
        }
        // B tile: 32 k x 128 cols (1024 float4, 4 per thread)
#pragma unroll
        for (int i = 0; i < 4; i++) {
            int fi = t + i * 256;
            int kr = fi >> 5;            // 32 float4 per row
            int cq = fi & 31;
            *(float4*)&Bs[kr][cq * 4] = *(const float4*)&B[(k0 + kr) * 128 + cq * 4];
        }
        __syncthreads();
#pragma unroll
        for (int kk = 0; kk < 32; kk++) {
            float4 av = *(float4*)&As[kk][ty * 4];
            float4 b0 = *(float4*)&Bs[kk][tx * 8];
            float4 b1 = *(float4*)&Bs[kk][tx * 8 + 4];
            float a[4] = {av.x, av.y, av.z, av.w};
            float b[8] = {b0.x, b0.y, b0.z, b0.w, b1.x, b1.y, b1.z, b1.w};
#pragma unroll
            for (int i = 0; i < 4; i++)
#pragma unroll
                for (int j = 0; j < 8; j++) acc[i][j] += a[i] * b[j];
        }
        __syncthreads();
    }
#pragma unroll
    for (int i = 0; i < 4; i++) {
        int grow = row0 + ty * 4 + i;
        if (grow < NN) {
            float ds = g_dis[grow];
            float4 v0 = make_float4(acc[i][0] * ds, acc[i][1] * ds, acc[i][2] * ds, acc[i][3] * ds);
            float4 v1 = make_float4(acc[i][4] * ds, acc[i][5] * ds, acc[i][6] * ds, acc[i][7] * ds);
            *(float4*)&g_hs[grow * 128 + tx * 8] = v0;
            *(float4*)&g_hs[grow * 128 + tx * 8 + 4] = v1;
        }
    }
}

// ---------------- CSR pull aggregation: warp per node ----------------
// agg[n] = dis[n] * (sum_{s in N(n)} hs[s] + hs[n]) + bias
__global__ void k_aggregate(const float* __restrict__ bias) {
    int t = blockIdx.x * blockDim.x + threadIdx.x;
    int n = t >> 5, q = t & 31;
    if (n >= NN) return;
    int beg = g_rowptr[n], end = g_rowptr[n + 1];
    float4 acc = ((const float4*)g_hs)[n * 32 + q];   // self term (pre-scaled)
    for (int i = beg; i < end; i++) {
        int s = g_csrsrc[i];                          // warp-uniform broadcast
        float4 v = ((const float4*)g_hs)[s * 32 + q];
        acc.x += v.x; acc.y += v.y; acc.z += v.z; acc.w += v.w;
    }
    float d = g_dis[n];
    float4 b = ((const float4*)bias)[q];
    acc.x = acc.x * d + b.x;
    acc.y = acc.y * d + b.y;
    acc.z = acc.z * d + b.z;
    acc.w = acc.w * d + b.w;
    ((float4*)g_agg)[n * 32 + q] = acc;
}

// ---------------- BN stats ----------------
__global__ void k_zero_stats() {
    int t = threadIdx.x;
    g_sum[t] = 0.0f;
    g_sumsq[t] = 0.0f;
}

__global__ void k_bnstats() {
    int c = threadIdx.x;
    float s = 0.0f, ss = 0.0f;
    for (int n = blockIdx.x; n < NN; n += gridDim.x) {
        float v = g_agg[n * HH + c];
        s += v;
        ss += v * v;
    }
    atomicAdd(&g_sum[c], s);
    atomicAdd(&g_sumsq[c], ss);
}

__global__ void k_bnfinal(const float* __restrict__ gamma, const float* __restrict__ beta) {
    int c = threadIdx.x;
    const float invN = 1.0f / (float)NN;
    float mu = g_sum[c] * invN;
    float var = g_sumsq[c] * invN - mu * mu;
    float sc = gamma[c] * rsqrtf(var + EPS);
    g_bnscale[c] = sc;
    g_bnshift[c] = beta[c] - mu * sc;
}

// ---------------- pooling (fused BN apply + relu) ----------------
__global__ void k_pool_zero() {
    int t = blockIdx.x * blockDim.x + threadIdx.x;
    if (t < GG * HH) g_pool[t] = 0.0f;
    if (t < GG) g_cnt[t] = 0.0f;
}

__global__ void k_pool(const int* __restrict__ batch) {
    int t = blockIdx.x * blockDim.x + threadIdx.x;
    int n = t >> 5, q = t & 31;
    if (n >= NN) return;
    int g = batch[n];
    float4 v  = ((const float4*)g_agg)[n * 32 + q];
    float4 sc = ((const float4*)g_bnscale)[q];
    float4 sh = ((const float4*)g_bnshift)[q];
    float4 o;
    o.x = fmaxf(v.x * sc.x + sh.x, 0.f);
    o.y = fmaxf(v.y * sc.y + sh.y, 0.f);
    o.z = fmaxf(v.z * sc.z + sh.z, 0.f);
    o.w = fmaxf(v.w * sc.w + sh.w, 0.f);
    float* out = g_pool + (size_t)g * HH + q * 4;
    asm volatile("red.global.add.v4.f32 [%0], {%1,%2,%3,%4};"
                 :: "l"(out), "f"(o.x), "f"(o.y), "f"(o.z), "f"(o.w)
                 : "memory");
    if (q == 0) atomicAdd(&g_cnt[g], 1.0f);
}

// ---------------- MLP head: one block per graph ----------------
__global__ void k_mlp(const float* __restrict__ w1, const float* __restrict__ b1,
                      const float* __restrict__ w2, const float* __restrict__ b2,
                      float* __restrict__ out) {
    int g = blockIdx.x;
    int t = threadIdx.x;       // 128
    __shared__ float p[128];
    __shared__ float red[4][8];
    float inv = 1.0f / fmaxf(g_cnt[g], 1.0f);
    p[t] = g_pool[g * HH + t] * inv;
    __syncthreads();
    float acc = b1[t];
#pragma unroll 8
    for (int k = 0; k < 128; k++) acc += p[k] * w1[k * 128 + t];
    float h = fmaxf(acc, 0.0f);
    float pr[CC];
#pragma unroll
    for (int c = 0; c < CC; c++) pr[c] = h * w2[t * CC + c];
#pragma unroll
    for (int off = 16; off > 0; off >>= 1)
#pragma unroll
        for (int c = 0; c < CC; c++) pr[c] += __shfl_down_sync(0xffffffffu, pr[c], off);
    int w = t >> 5, lane = t & 31;
    if (lane == 0)
#pragma unroll
        for (int c = 0; c < CC; c++) red[w][c] = pr[c];
    __syncthreads();
    if (t < CC) {
        out[g * CC + t] = red[0][t] + red[1][t] + red[2][t] + red[3][t] + b2[t];
    }
}

// ---------------- launch ----------------
extern "C" void kernel_launch(void* const* d_in, const int* in_sizes, int n_in,
                              void* d_out, int out_size) {
    const float* x      = (const float*)d_in[0];
    const int*   ei     = (const int*)d_in[1];
    const int*   batch  = (const int*)d_in[2];
    const float* conv_w = (const float*)d_in[3];
    const float* conv_b = (const float*)d_in[4];
    const float* bn_g   = (const float*)d_in[5];
    const float* bn_b   = (const float*)d_in[6];
    const float* w1     = (const float*)d_in[7];
    const float* b1     = (const float*)d_in[8];
    const float* w2     = (const float*)d_in[9];
    const float* b2     = (const float*)d_in[10];
    float* out = (float*)d_out;

    const int* src = ei;
    const int* dst = ei + EE;

    // CSR build + norms
    k_zero_degi<<<(NN + 255) / 256, 256>>>();
    k_deg_count<<<(EE + 255) / 256, 256>>>(dst);
    k_norm<<<(NN + 255) / 256, 256>>>();
    k_scan<<<1, 1024>>>();
    k_fill<<<(EE + 255) / 256, 256>>>(src, dst);

    const int ggrid = (NN + 63) / 64;
    const long long nwarp_threads = (long long)NN * 32;
    const int nwarp_blocks = (int)((nwarp_threads + 255) / 256);

    for (int l = 0; l < LL; l++) {
        const float* A = (l == 0) ? x : nullptr;   // nullptr -> g_agg with BN prologue
        k_gemm<<<ggrid, 256>>>(A, conv_w + (size_t)l * HH * HH, l > 0 ? 1 : 0);
        k_aggregate<<<nwarp_blocks, 256>>>(conv_b + (size_t)l * HH);
        k_zero_stats<<<1, 128>>>();
        k_bnstats<<<1024, 128>>>();
        k_bnfinal<<<1, 128>>>(bn_g + (size_t)l * HH, bn_b + (size_t)l * HH);
    }

    k_pool_zero<<<(GG * HH + 255) / 256, 256>>>();
    k_pool<<<nwarp_blocks, 256>>>(batch);
    k_mlp<<<GG, 128>>>(w1, b1, w2, b2, out);
}